// round 3
// baseline (speedup 1.0000x reference)
#include <cuda_runtime.h>

// LatentLinearModel: r[i] = dot(U[users[i]], V[jokes[i]]) + a[users[i]] + b[jokes[i]] + g
// B = 1048576 rows, K = 64.
//
// Round 3: amortize the DRAM latency window over more bytes per warp task
// cycle. Each 16-lane group handles 8 rows; all 16 gather LDG.128s are issued
// before any consumption (8 KB in flight per warp). Indices loaded as int4.
// Occupancy deliberately sacrificed (regs ~100) for per-warp MLP=16: the
// per-SM L1tex in-flight queue stays full for the whole cycle.

#define TPR   16        // threads per row
#define RPG   8         // rows per 16-lane group
#define BLOCK 256

__global__ void __launch_bounds__(BLOCK)
latent_linear_kernel(const int* __restrict__ users,
                     const int* __restrict__ jokes,
                     const float4* __restrict__ U4,
                     const float4* __restrict__ V4,
                     const float* __restrict__ a,
                     const float* __restrict__ b,
                     const float* __restrict__ g,
                     float* __restrict__ out,
                     int B) {
    int lane = threadIdx.x & (TPR - 1);
    int gid  = (blockIdx.x * BLOCK + threadIdx.x) >> 4;   // group id
    int row0 = gid * RPG;
    if (row0 >= B) return;

    // ---- Phase 1: vectorized index loads (row0 is a multiple of 8 -> 16B aligned) ----
    int4 ua = __ldg((const int4*)(users + row0));
    int4 ub = __ldg((const int4*)(users + row0) + 1);
    int4 ja = __ldg((const int4*)(jokes + row0));
    int4 jb = __ldg((const int4*)(jokes + row0) + 1);
    int us[RPG] = {ua.x, ua.y, ua.z, ua.w, ub.x, ub.y, ub.z, ub.w};
    int js[RPG] = {ja.x, ja.y, ja.z, ja.w, jb.x, jb.y, jb.z, jb.w};

    // ---- Phase 2: issue ALL 16 gathers before any use (8KB in flight / warp) ----
    float4 uu[RPG], vv[RPG];
#pragma unroll
    for (int r = 0; r < RPG; r++) {
        uu[r] = __ldg(&U4[(size_t)us[r] * 16 + lane]);
        vv[r] = __ldg(&V4[(size_t)js[r] * 16 + lane]);
    }

    // Bias loads in flight concurrently with the gathers (lane 0 only).
    float bias[RPG];
    if (lane == 0) {
#pragma unroll
        for (int r = 0; r < RPG; r++) {
            bias[r] = __ldg(&a[us[r]]) + __ldg(&b[js[r]]);
        }
    }
    float gg = __ldg(&g[0]);

    // ---- Phase 3: dot + 16-lane reduction per row ----
#pragma unroll
    for (int r = 0; r < RPG; r++) {
        float d = uu[r].x * vv[r].x + uu[r].y * vv[r].y
                + uu[r].z * vv[r].z + uu[r].w * vv[r].w;
        d += __shfl_xor_sync(0xffffffffu, d, 8);
        d += __shfl_xor_sync(0xffffffffu, d, 4);
        d += __shfl_xor_sync(0xffffffffu, d, 2);
        d += __shfl_xor_sync(0xffffffffu, d, 1);
        if (lane == 0) {
            out[row0 + r] = d + bias[r] + gg;
        }
    }
}

extern "C" void kernel_launch(void* const* d_in, const int* in_sizes, int n_in,
                              void* d_out, int out_size) {
    // metadata order: users, jokes, U, V, a, b, g
    const int*    users = (const int*)d_in[0];
    const int*    jokes = (const int*)d_in[1];
    const float4* U4    = (const float4*)d_in[2];
    const float4* V4    = (const float4*)d_in[3];
    const float*  a     = (const float*)d_in[4];
    const float*  b     = (const float*)d_in[5];
    const float*  g     = (const float*)d_in[6];
    float* out = (float*)d_out;

    int B = in_sizes[0];

    int rows_per_block = (BLOCK / TPR) * RPG;   // 128
    int grid = (B + rows_per_block - 1) / rows_per_block;
    latent_linear_kernel<<<grid, BLOCK>>>(users, jokes, U4, V4, a, b, g, out, B);
}

// round 4
// speedup vs baseline: 1.1411x; 1.1411x over previous
#include <cuda_runtime.h>

// LatentLinearModel: r[i] = dot(U[users[i]], V[jokes[i]]) + a[users[i]] + b[jokes[i]] + g
// B = 1048576, K = 64.
//
// Round 4: cp.async (LDGSTS) gathers -> shared memory. In-flight bytes no
// longer consume registers, so high occupancy AND high per-warp MLP coexist:
// ~48 warps/SM x 8 outstanding 16B gathers each (~384 in flight) vs 272 (R2).
// Each thread reads back only its own smem slots, so cp.async.wait_group is
// the only synchronization needed (no __syncthreads).

#define TPR   16                    // threads per row
#define RPG   4                     // rows per 16-lane group
#define BLOCK 256
#define GROUPS (BLOCK / TPR)        // 16
#define RPB   (GROUPS * RPG)        // 64 rows per block

__device__ __forceinline__ void cp_async16(void* smem, const void* gmem) {
    unsigned s = (unsigned)__cvta_generic_to_shared(smem);
    asm volatile("cp.async.cg.shared.global [%0], [%1], 16;" :: "r"(s), "l"(gmem));
}

__global__ void __launch_bounds__(BLOCK)
latent_linear_kernel(const int* __restrict__ users,
                     const int* __restrict__ jokes,
                     const float4* __restrict__ U4,
                     const float4* __restrict__ V4,
                     const float* __restrict__ a,
                     const float* __restrict__ b,
                     const float* __restrict__ g,
                     float* __restrict__ out,
                     int B) {
    __shared__ float4 sU[RPB][TPR];   // 16 KB
    __shared__ float4 sV[RPB][TPR];   // 16 KB

    int lane  = threadIdx.x & (TPR - 1);
    int group = threadIdx.x >> 4;
    int lrow0 = group * RPG;                       // local row base in smem
    int row0  = blockIdx.x * RPB + lrow0;          // global row base
    if (row0 >= B) return;

    // ---- Phase 1: vectorized index loads (row0 multiple of 4 -> 16B aligned) ----
    int4 ui = __ldg((const int4*)(users + row0));
    int4 ji = __ldg((const int4*)(jokes + row0));
    int us[RPG] = {ui.x, ui.y, ui.z, ui.w};
    int js[RPG] = {ji.x, ji.y, ji.z, ji.w};

    // ---- Phase 2: issue all 8 gathers per thread as cp.async (no reg cost) ----
#pragma unroll
    for (int r = 0; r < RPG; r++) {
        cp_async16(&sU[lrow0 + r][lane], &U4[(size_t)us[r] * 16 + lane]);
        cp_async16(&sV[lrow0 + r][lane], &V4[(size_t)js[r] * 16 + lane]);
    }
    asm volatile("cp.async.commit_group;");

    // Bias loads fly concurrently with the cp.asyncs (lane 0 only).
    float bias[RPG];
    if (lane == 0) {
#pragma unroll
        for (int r = 0; r < RPG; r++) {
            bias[r] = __ldg(&a[us[r]]) + __ldg(&b[js[r]]);
        }
    }
    float gg = __ldg(&g[0]);

    asm volatile("cp.async.wait_group 0;" ::: "memory");

    // ---- Phase 3: dot + 16-lane reduction per row (each thread reads its own slots) ----
#pragma unroll
    for (int r = 0; r < RPG; r++) {
        float4 uu = sU[lrow0 + r][lane];
        float4 vv = sV[lrow0 + r][lane];
        float d = uu.x * vv.x + uu.y * vv.y + uu.z * vv.z + uu.w * vv.w;
        d += __shfl_xor_sync(0xffffffffu, d, 8);
        d += __shfl_xor_sync(0xffffffffu, d, 4);
        d += __shfl_xor_sync(0xffffffffu, d, 2);
        d += __shfl_xor_sync(0xffffffffu, d, 1);
        if (lane == 0) {
            out[row0 + r] = d + bias[r] + gg;
        }
    }
}

extern "C" void kernel_launch(void* const* d_in, const int* in_sizes, int n_in,
                              void* d_out, int out_size) {
    // metadata order: users, jokes, U, V, a, b, g
    const int*    users = (const int*)d_in[0];
    const int*    jokes = (const int*)d_in[1];
    const float4* U4    = (const float4*)d_in[2];
    const float4* V4    = (const float4*)d_in[3];
    const float*  a     = (const float*)d_in[4];
    const float*  b     = (const float*)d_in[5];
    const float*  g     = (const float*)d_in[6];
    float* out = (float*)d_out;

    int B = in_sizes[0];

    int grid = (B + RPB - 1) / RPB;
    latent_linear_kernel<<<grid, BLOCK>>>(users, jokes, U4, V4, a, b, g, out, B);
}